// round 16
// baseline (speedup 1.0000x reference)
#include <cuda_runtime.h>
#include <cuda_fp16.h>
#include <cstdint>

#define Bb 16
#define Cc 306
#define Tt 4096
#define Mm 270
#define Gg 64
#define TT 256            // t-tile per CTA
#define NTH 256

#define A1PITCH 72
#define XPITCH  264
#define GPITCH  264
#define WPITCH  72
// smem layout (bytes):
//   phase 1: S  [0, 46080)      5 x [64][72] fp16 (stride 9216; 64-wide k blocks), built in-CTA
//            X0 [46080, 62976)  [32][264] fp16 (one 32-channel chunk)
//            X1 [62976, 79872)
//   phase 2 overlays (after all phase-1 reads):
//            GV [0, 33792)      [64][264] fp16
//            W  [33792, 75264)  [288][72] fp16 (rows >= 270 unwritten; stores guarded)
#define SM_S    0
#define SM_X0   46080
#define SM_X1   62976
#define SM_GV   0
#define SM_W    33792
#define SM_TOTAL 79872

__device__ __forceinline__ uint32_t smem_u32(const void* p) {
    uint32_t a;
    asm("{ .reg .u64 t; cvta.to.shared.u64 t, %1; cvt.u32.u64 %0, t; }" : "=r"(a) : "l"(p));
    return a;
}
__device__ __forceinline__ void ldsm_x4(uint32_t* r, uint32_t addr) {
    asm volatile("ldmatrix.sync.aligned.m8n8.x4.shared.b16 {%0,%1,%2,%3}, [%4];"
                 : "=r"(r[0]), "=r"(r[1]), "=r"(r[2]), "=r"(r[3]) : "r"(addr));
}
__device__ __forceinline__ void ldsm_x4_t(uint32_t* r, uint32_t addr) {
    asm volatile("ldmatrix.sync.aligned.m8n8.x4.trans.shared.b16 {%0,%1,%2,%3}, [%4];"
                 : "=r"(r[0]), "=r"(r[1]), "=r"(r[2]), "=r"(r[3]) : "r"(addr));
}
__device__ __forceinline__ void mma16816(float* c, const uint32_t* a, const uint32_t* b) {
    asm volatile(
        "mma.sync.aligned.m16n8k16.row.col.f32.f16.f16.f32 "
        "{%0,%1,%2,%3}, {%4,%5,%6,%7}, {%8,%9}, {%0,%1,%2,%3};"
        : "+f"(c[0]), "+f"(c[1]), "+f"(c[2]), "+f"(c[3])
        : "r"(a[0]), "r"(a[1]), "r"(a[2]), "r"(a[3]), "r"(b[0]), "r"(b[1]));
}

// In-quad transpose: source lane a holds local-t {2a,2a+1} (x0,x1) and {8+2a,8+2a+1} (y0,y1);
// target lane q returns float4 covering local-t [4q, 4q+3].
__device__ __forceinline__ float4 quad_t4(float x0, float x1, float y0, float y1, int lane) {
    int q = lane & 3;
    int s0 = (2 * q) & 3;
    int s1 = (2 * q + 1) & 3;
    float a0 = __shfl_sync(0xffffffffu, x0, s0, 4);
    float a1 = __shfl_sync(0xffffffffu, x1, s0, 4);
    float a2 = __shfl_sync(0xffffffffu, x0, s1, 4);
    float a3 = __shfl_sync(0xffffffffu, x1, s1, 4);
    float b0 = __shfl_sync(0xffffffffu, y0, s0, 4);
    float b1 = __shfl_sync(0xffffffffu, y1, s0, 4);
    float b2 = __shfl_sync(0xffffffffu, y0, s1, 4);
    float b3 = __shfl_sync(0xffffffffu, y1, s1, 4);
    return (q < 2) ? make_float4(a0, a1, a2, a3) : make_float4(b0, b1, b2, b3);
}

__global__ void __launch_bounds__(NTH, 2)
fused_kernel(const float* __restrict__ x, const float* __restrict__ pos,
             const float* __restrict__ W, float* __restrict__ out) {
    extern __shared__ char smem[];
    const uint32_t sb = smem_u32(smem);
    const int tid = threadIdx.x;
    const int wid = tid >> 5;           // 0..7
    const int lane = tid & 31;

    const int t0 = blockIdx.x * TT;
    const int b  = blockIdx.y;

    const int arow = lane & 15;
    const int acol = (lane >> 4) * 8;

    // ---- 1. pos loads (issue early) ----
    float2 pA = make_float2(0.f, 0.f), pB = make_float2(0.f, 0.f);
    if (tid < Cc) pA = *(const float2*)(pos + ((size_t)b * Cc + tid) * 2);
    if (tid < Cc - 256) pB = *(const float2*)(pos + ((size_t)b * Cc + 256 + tid) * 2);

    // ---- 2. x chunk0 LDGs (32 channels x 256 t; fly under S build) ----
    float4 xv[8];
    auto load_X = [&](int c0) {   // c0 = channel offset, chunk = 32 channels
#pragma unroll
        for (int it = 0; it < 8; it++) {
            int r = wid * 4 + (it >> 1);          // 0..31
            int cg = c0 + r;
            int half = it & 1;                    // t halves of 128
            xv[it] = (cg < Cc)
                ? *(const float4*)(x + ((size_t)(b * Cc + cg)) * Tt + t0 + half * 128 + lane * 4)
                : make_float4(0.f, 0.f, 0.f, 0.f);
        }
    };
    load_X(0);

    // ---- 3. zero S region (46080 B = 2880 uint4) ----
    {
        uint4 z = make_uint4(0, 0, 0, 0);
#pragma unroll
        for (int it = 0; it < 12; it++) {
            int idx = tid + it * NTH;
            if (idx < 2880) ((uint4*)smem)[idx] = z;
        }
    }
    __syncthreads();   // zeroing complete before any scatter write

    // ---- 4. scatter-build S (fp16) with duplicate-corner merge ----
    auto scat = [&](int c, float2 p) {
        float gp0 = (p.x + 1.0f) * 4.0f;
        float gp1 = (p.y + 1.0f) * 4.0f;
        float f0 = floorf(gp0), f1 = floorf(gp1);
        int il0 = min(7, max(0, (int)f0)), il1 = min(7, max(0, (int)f1));
        int ih0 = min(7, max(0, (int)ceilf(gp0))), ih1 = min(7, max(0, (int)ceilf(gp1)));
        float wh0 = gp0 - f0, wl0 = 1.0f - wh0;
        float wh1 = gp1 - f1, wl1 = 1.0f - wh1;
        float w00 = wl0 * wl1, w01 = wl0 * wh1, w10 = wh0 * wl1, w11 = wh0 * wh1;
        bool d0 = (ih0 == il0), d1 = (ih1 == il1);
        if (d0) { w00 += w10; w01 += w11; }
        if (d1) { w00 += w01; w10 += w11; }
        char* base = smem + SM_S + (c >> 6) * 9216 + (c & 63) * 2;
        *(__half*)(base + (il0 * 8 + il1) * (A1PITCH * 2)) = __float2half_rn(w00);
        if (!d1)        *(__half*)(base + (il0 * 8 + ih1) * (A1PITCH * 2)) = __float2half_rn(w01);
        if (!d0)        *(__half*)(base + (ih0 * 8 + il1) * (A1PITCH * 2)) = __float2half_rn(w10);
        if (!d0 && !d1) *(__half*)(base + (ih0 * 8 + ih1) * (A1PITCH * 2)) = __float2half_rn(w11);
    };
    if (tid < Cc) scat(tid, pA);
    if (tid < Cc - 256) scat(tid + 256, pB);

    // ---- 5. stage x chunk0, prefetch chunk1 ----
    auto stsX = [&](int buf) {
        char* base = smem + (buf ? SM_X1 : SM_X0);
#pragma unroll
        for (int it = 0; it < 8; it++) {
            int r = wid * 4 + (it >> 1);
            int half = it & 1;
            float4 v = xv[it];
            __half2 h0 = __floats2half2_rn(v.x, v.y);
            __half2 h1 = __floats2half2_rn(v.z, v.w);
            uint32_t boff = (r * XPITCH + half * 128 + lane * 4) * 2;
            *(uint2*)(base + boff) = make_uint2(*(uint32_t*)&h0, *(uint32_t*)&h1);
        }
    };
    stsX(0);
    load_X(32);
    __syncthreads();

    // ======== phase 1: gv[64 x 256] = S_b @ x_tile (single fp16) ========
    // 8 warps as 2m x 4t; warp tile 32m x 64t
    const int wm1 = wid >> 2;           // 0..1
    const int wt1 = wid & 3;            // 0..3

    float gacc[2][8][4];
#pragma unroll
    for (int i = 0; i < 2; i++)
#pragma unroll
        for (int j = 0; j < 8; j++)
#pragma unroll
            for (int q = 0; q < 4; q++) gacc[i][j][q] = 0.0f;

    auto mma1 = [&](int kcc, int xb) {   // kcc = 32-wide chunk index (0..9)
        uint32_t baseA = sb + SM_S + (kcc >> 1) * 9216;
        const int kbase = (kcc & 1) * 32;
        uint32_t baseB = sb + (xb ? SM_X1 : SM_X0);
#pragma unroll
        for (int ks = 0; ks < 2; ks++) {
            uint32_t ah[2][4];
#pragma unroll
            for (int i = 0; i < 2; i++) {
                uint32_t off = ((wm1 * 32 + i * 16 + arow) * A1PITCH + kbase + ks * 16 + acol) * 2;
                ldsm_x4(ah[i], baseA + off);
            }
#pragma unroll
            for (int j2 = 0; j2 < 4; j2++) {
                uint32_t off = ((ks * 16 + arow) * XPITCH + wt1 * 64 + j2 * 16 + acol) * 2;
                uint32_t bh[4];
                ldsm_x4_t(bh, baseB + off);
#pragma unroll
                for (int jh = 0; jh < 2; jh++) {
                    int j = j2 * 2 + jh;
#pragma unroll
                    for (int i = 0; i < 2; i++)
                        mma16816(gacc[i][j], ah[i], &bh[jh * 2]);
                }
            }
        }
    };

    for (int kcc = 0; kcc < 10; kcc++) {
        mma1(kcc, kcc & 1);
        if (kcc < 9) {
            stsX((kcc + 1) & 1);                   // x(kcc+1) from regs (other buffer)
            if (kcc < 8) load_X((kcc + 2) * 32);   // flies under next MMA
            __syncthreads();
        }
    }
    __syncthreads();                               // all phase-1 reads done before overlays

    // ======== transition: gv (fp16) + W convert into smem ========
    {
        int r0 = wm1 * 32 + (lane >> 2);
#pragma unroll
        for (int i = 0; i < 2; i++) {
            int ra = r0 + i * 16, rb = ra + 8;
#pragma unroll
            for (int j = 0; j < 8; j++) {
                int t = wt1 * 64 + j * 8 + (lane & 3) * 2;
                __half2 h0 = __floats2half2_rn(gacc[i][j][0], gacc[i][j][1]);
                __half2 h1 = __floats2half2_rn(gacc[i][j][2], gacc[i][j][3]);
                *(uint32_t*)(smem + SM_GV + (ra * GPITCH + t) * 2) = *(uint32_t*)&h0;
                *(uint32_t*)(smem + SM_GV + (rb * GPITCH + t) * 2) = *(uint32_t*)&h1;
            }
        }
    }
    // W fp32 -> fp16 (270 rows x 64 cols; rows >= 270 unwritten, stores guarded)
    {
#pragma unroll
        for (int it = 0; it < 17; it++) {
            int idx = tid + it * NTH;      // valid < 4320
            if (idx < Mm * 16) {
                int r = idx >> 4, q = idx & 15;
                float4 v = *(const float4*)(W + r * 64 + q * 4);
                __half2 a = __floats2half2_rn(v.x, v.y);
                __half2 c = __floats2half2_rn(v.z, v.w);
                char* d = smem + SM_W + (r * WPITCH + q * 4) * 2;
                *(uint32_t*)d       = *(uint32_t*)&a;
                *(uint32_t*)(d + 4) = *(uint32_t*)&c;
            }
        }
    }
    __syncthreads();

    // ======== phase 2: out = W @ gv (single fp16), no internal barriers ========
    // 8 warps as 1m x 8t; warp tile 48m x 32t; 6 m-chunks of 48
    const int wt2 = wid;                // 0..7

#pragma unroll 1
    for (int mc = 0; mc < 6; mc++) {
        const int m0 = mc * 48;
        float acc[3][4][4];
#pragma unroll
        for (int i = 0; i < 3; i++)
#pragma unroll
            for (int j = 0; j < 4; j++)
#pragma unroll
                for (int q = 0; q < 4; q++) acc[i][j][q] = 0.0f;

#pragma unroll
        for (int ks = 0; ks < 4; ks++) {
            const int k0 = ks * 16;
            uint32_t ah[3][4];
#pragma unroll
            for (int i = 0; i < 3; i++) {
                uint32_t off = ((m0 + i * 16 + arow) * WPITCH + k0 + acol) * 2;
                ldsm_x4(ah[i], sb + SM_W + off);
            }
#pragma unroll
            for (int j2 = 0; j2 < 2; j2++) {
                uint32_t off = ((k0 + arow) * GPITCH + wt2 * 32 + j2 * 16 + acol) * 2;
                uint32_t bh[4];
                ldsm_x4_t(bh, sb + SM_GV + off);
#pragma unroll
                for (int jh = 0; jh < 2; jh++) {
                    int j = j2 * 2 + jh;
#pragma unroll
                    for (int i = 0; i < 3; i++)
                        mma16816(acc[i][j], ah[i], &bh[jh * 2]);
                }
            }
        }

        // epilogue: in-quad transpose -> coalesced STG.128 (64B contiguous per row-quad)
#pragma unroll
        for (int i = 0; i < 3; i++) {
            int mlo = m0 + i * 16 + (lane >> 2);
            int mhi = mlo + 8;
#pragma unroll
            for (int jp = 0; jp < 2; jp++) {
                float4 lo = quad_t4(acc[i][2 * jp][0], acc[i][2 * jp][1],
                                    acc[i][2 * jp + 1][0], acc[i][2 * jp + 1][1], lane);
                float4 hi = quad_t4(acc[i][2 * jp][2], acc[i][2 * jp][3],
                                    acc[i][2 * jp + 1][2], acc[i][2 * jp + 1][3], lane);
                int t = t0 + wt2 * 32 + jp * 16 + (lane & 3) * 4;
                if (mlo < Mm)
                    *(float4*)&out[((size_t)b * Mm + mlo) * Tt + t] = lo;
                if (mhi < Mm)
                    *(float4*)&out[((size_t)b * Mm + mhi) * Tt + t] = hi;
            }
        }
    }
}

// ---------------- launch: single kernel, single wave ----------------
extern "C" void kernel_launch(void* const* d_in, const int* in_sizes, int n_in,
                              void* d_out, int out_size) {
    const float* x   = (const float*)d_in[0];  // [B, C, T]
    const float* pos = (const float*)d_in[1];  // [B, C, 2]
    const float* W   = (const float*)d_in[2];  // [M, G]
    float* out = (float*)d_out;                // [B, M, T]

    cudaFuncSetAttribute(fused_kernel, cudaFuncAttributeMaxDynamicSharedMemorySize, SM_TOTAL);
    fused_kernel<<<dim3(Tt / TT, Bb), NTH, SM_TOTAL>>>(x, pos, W, out);
}